// round 3
// baseline (speedup 1.0000x reference)
#include <cuda_runtime.h>

// Shapes (fixed by the problem)
#define Bb 256
#define Cc 256
#define CH 128
#define NN 196               // H*W = 14*14
#define N4 49                // float4s per channel row
#define TOT_F4 (Bb * Cc * N4)   // 3,211,264
#define EPS 1e-5f

// K2 geometry: exact tiling, no bounds checks.
// 1568 blocks * 512 threads * 4 f4/thread = 3,211,264 = TOT_F4
#define K2_BLOCKS 1568
#define K2_THREADS 512
#define K2_STRIDE (K2_BLOCKS * K2_THREADS)

__device__ float g_zbn[Bb * Cc];    // per-(b,o) BN-folded bias term

// ---------------------------------------------------------------------------
// K1: one block per batch (512 thr).
//   Phase 1: ys[c] = sum_n y[b,c,n]          (warp per channel, 16 ch/warp)
//   Phase 2: zbn = BN(Wz @ (Wv @ ys))        (softmax==1 collapse; Wq,Wk dead)
// Ends with threadfence + programmatic-launch trigger so K2 can overlap.
// ---------------------------------------------------------------------------
__global__ void __launch_bounds__(512, 2)
k_zbn(const float* __restrict__ y,
      const float* __restrict__ Wv,
      const float* __restrict__ Wz,
      const float* __restrict__ bn_w,
      const float* __restrict__ bn_b,
      const float* __restrict__ bn_m,
      const float* __restrict__ bn_v) {
    __shared__ float ys[Cc];
    __shared__ float tmp[CH];

    const int b    = blockIdx.x;
    const int t    = threadIdx.x;
    const int warp = t >> 5;
    const int lane = t & 31;

    const float4* yb = reinterpret_cast<const float4*>(y + (size_t)b * (Cc * NN));

    // ---- Phase 1: spatial sums (coalesced; front-batched pair of loads) ----
    #pragma unroll 4
    for (int k = 0; k < 16; k++) {
        const int ch = warp * 16 + k;
        const float4* row = yb + ch * N4;
        float4 v = row[lane];
        float4 w2 = (lane < N4 - 32) ? row[lane + 32]
                                     : make_float4(0.f, 0.f, 0.f, 0.f);
        float s = v.x + v.y + v.z + v.w + w2.x + w2.y + w2.z + w2.w;
        #pragma unroll
        for (int o = 16; o; o >>= 1) s += __shfl_xor_sync(0xFFFFFFFFu, s, o);
        if (lane == 0) ys[ch] = s;
    }
    __syncthreads();

    // ---- Phase 2a: tmp[ch] = Wv[ch,:] . ys  (4 threads per ch) ----
    {
        const int ch = t >> 2, part = t & 3;
        const float4* wr = reinterpret_cast<const float4*>(Wv + ch * Cc) + part * 16;
        const float* yss = ys + part * 64;
        float acc = 0.0f;
        #pragma unroll
        for (int i = 0; i < 16; i++) {
            float4 v = wr[i];
            acc += v.x * yss[4*i]   + v.y * yss[4*i+1]
                 + v.z * yss[4*i+2] + v.w * yss[4*i+3];
        }
        acc += __shfl_xor_sync(0xFFFFFFFFu, acc, 1);
        acc += __shfl_xor_sync(0xFFFFFFFFu, acc, 2);
        if (part == 0) tmp[ch] = acc;
    }
    __syncthreads();

    // ---- Phase 2b: z[o] = Wz[o,:] . tmp, BN fold  (2 threads per o) ----
    {
        const int o = t >> 1, part = t & 1;
        const float4* wr = reinterpret_cast<const float4*>(Wz + o * CH) + part * 16;
        const float* tp = tmp + part * 64;
        float acc = 0.0f;
        #pragma unroll
        for (int i = 0; i < 16; i++) {
            float4 v = wr[i];
            acc += v.x * tp[4*i]   + v.y * tp[4*i+1]
                 + v.z * tp[4*i+2] + v.w * tp[4*i+3];
        }
        acc += __shfl_xor_sync(0xFFFFFFFFu, acc, 1);
        if (part == 0) {
            const float inv = rsqrtf(bn_v[o] + EPS);
            g_zbn[b * Cc + o] = (acc - bn_m[o]) * inv * bn_w[o] + bn_b[o];
        }
    }

    __threadfence();                              // make zbn globally visible
    cudaTriggerProgrammaticLaunchCompletion();    // release PDL-gated K2
}

// ---------------------------------------------------------------------------
// K2: out[i] = x[i] + zbn[i / 49]  over float4s.
// Front-batches 4 independent LDG.128 (MLP=4) BEFORE the PDL dependency sync,
// so x-streaming overlaps K1's tail. Exact tiling -> no bounds checks.
// ---------------------------------------------------------------------------
__global__ void __launch_bounds__(K2_THREADS)
k_out(const float* __restrict__ x, float* __restrict__ out) {
    const int tid = blockIdx.x * K2_THREADS + threadIdx.x;
    const float4* x4 = reinterpret_cast<const float4*>(x);
    float4*       o4 = reinterpret_cast<float4*>(out);

    float4 v0 = x4[tid + 0 * K2_STRIDE];
    float4 v1 = x4[tid + 1 * K2_STRIDE];
    float4 v2 = x4[tid + 2 * K2_STRIDE];
    float4 v3 = x4[tid + 3 * K2_STRIDE];

    cudaGridDependencySynchronize();              // wait for K1's zbn

    const float z0 = __ldg(&g_zbn[(tid + 0 * K2_STRIDE) / N4]);
    const float z1 = __ldg(&g_zbn[(tid + 1 * K2_STRIDE) / N4]);
    const float z2 = __ldg(&g_zbn[(tid + 2 * K2_STRIDE) / N4]);
    const float z3 = __ldg(&g_zbn[(tid + 3 * K2_STRIDE) / N4]);

    v0.x += z0; v0.y += z0; v0.z += z0; v0.w += z0;
    v1.x += z1; v1.y += z1; v1.z += z1; v1.w += z1;
    v2.x += z2; v2.y += z2; v2.z += z2; v2.w += z2;
    v3.x += z3; v3.y += z3; v3.z += z3; v3.w += z3;

    o4[tid + 0 * K2_STRIDE] = v0;
    o4[tid + 1 * K2_STRIDE] = v1;
    o4[tid + 2 * K2_STRIDE] = v2;
    o4[tid + 3 * K2_STRIDE] = v3;
}

// ---------------------------------------------------------------------------
// Inputs (metadata order):
//  0:x 1:y 2:Wq 3:Wk 4:Wv 5:Wz 6:bn_weight 7:bn_bias 8:bn_mean 9:bn_var
// ---------------------------------------------------------------------------
extern "C" void kernel_launch(void* const* d_in, const int* in_sizes, int n_in,
                              void* d_out, int out_size) {
    const float* x    = (const float*)d_in[0];
    const float* y    = (const float*)d_in[1];
    const float* Wv   = (const float*)d_in[4];
    const float* Wz   = (const float*)d_in[5];
    const float* bn_w = (const float*)d_in[6];
    const float* bn_b = (const float*)d_in[7];
    const float* bn_m = (const float*)d_in[8];
    const float* bn_v = (const float*)d_in[9];
    float* out = (float*)d_out;

    k_zbn<<<Bb, 512>>>(y, Wv, Wz, bn_w, bn_b, bn_m, bn_v);

    // Launch K2 with programmatic stream serialization: it may start while K1
    // runs; cudaGridDependencySynchronize() inside gates on K1's trigger.
    cudaLaunchConfig_t cfg = {};
    cfg.gridDim  = dim3(K2_BLOCKS, 1, 1);
    cfg.blockDim = dim3(K2_THREADS, 1, 1);
    cudaLaunchAttribute attr[1];
    attr[0].id = cudaLaunchAttributeProgrammaticStreamSerialization;
    attr[0].val.programmaticStreamSerializationAllowed = 1;
    cfg.attrs = attr;
    cfg.numAttrs = 1;
    cudaLaunchKernelEx(&cfg, k_out, x, out);
}